// round 17
// baseline (speedup 1.0000x reference)
#include <cuda_runtime.h>
#include <cuda_bf16.h>
#include <cuda_fp16.h>

#define S 2048
#define F 1024
#define H 16
#define DH 64
#define NHD 1024  // H*DH

typedef unsigned long long u64;
typedef unsigned int u32;

#define LOG2E 1.4426950408889634f
#define SCQ (0.125f * LOG2E)   // folded softmax scale + log2 conversion

// ---- f16 mma ----
__device__ __forceinline__ void mma_f16(float c[4], const u32 a[4], u32 b0, u32 b1) {
    asm volatile(
        "mma.sync.aligned.m16n8k16.row.col.f32.f16.f16.f32 "
        "{%0,%1,%2,%3}, {%4,%5,%6,%7}, {%8,%9}, {%0,%1,%2,%3};\n"
        : "+f"(c[0]), "+f"(c[1]), "+f"(c[2]), "+f"(c[3])
        : "r"(a[0]), "r"(a[1]), "r"(a[2]), "r"(a[3]), "r"(b0), "r"(b1));
}

__device__ __forceinline__ u32 exp2_f16x2(float ylo, float yhi) {
    __half2 h = __floats2half2_rn(ylo, yhi);
    __half2 r = h2exp2(h);
    return *(u32*)&r;
}

__device__ __forceinline__ void ldm2t(u32& d0, u32& d1, u32 saddr) {
    asm volatile("ldmatrix.sync.aligned.m8n8.x2.trans.shared.b16 {%0,%1}, [%2];"
                 : "=r"(d0), "=r"(d1) : "r"(saddr));
}
__device__ __forceinline__ void ldm2(u32& d0, u32& d1, u32 saddr) {
    asm volatile("ldmatrix.sync.aligned.m8n8.x2.shared.b16 {%0,%1}, [%2];"
                 : "=r"(d0), "=r"(d1) : "r"(saddr));
}
__device__ __forceinline__ u32 sptr(const void* p) {
    return (u32)__cvta_generic_to_shared(p);
}
__device__ __forceinline__ void pair_bar(int wp) {
    asm volatile("bar.sync %0, 64;" :: "r"(1 + wp) : "memory");
}
// ---- cp.async (global -> shared, 16B) ----
__device__ __forceinline__ void cpa16(u32 dst, const void* src) {
    asm volatile("cp.async.ca.shared.global [%0], [%1], 16;"
                 :: "r"(dst), "l"(src) : "memory");
}
#define CP_COMMIT() asm volatile("cp.async.commit_group;" ::: "memory")
#define CP_WAIT0()  asm volatile("cp.async.wait_group 0;" ::: "memory")

// Scratch (device globals: allocation-free per harness rules)
__device__ float g_ck[H * S];
__device__ float g_cr[H * S];
// f16 attention operands (emitted by proj epilogue)
__device__ __half g_q16[S * NHD];   // pre-scaled by SCQ
__device__ __half g_k16[S * NHD];
__device__ __half g_v16[S * NHD];
__device__ __half g_r16[S * NHD];
// f16 GEMM panels
__device__ __half g_xq[S * F];
__device__ __half g_xr[S * F];
__device__ __half g_w16[5 * F * NHD];             // Wq,Wk,Wv,Wr,Wo
__device__ __half g_at_h[S * NHD], g_at_l[S * NHD];

// ---------------------------------------------------------------------------
// Convert fp32 operands -> f16 panels.
// ---------------------------------------------------------------------------
__global__ __launch_bounds__(256) void split_kernel(
    const float* __restrict__ xq, const float* __restrict__ xr,
    const float* __restrict__ w0, const float* __restrict__ w1,
    const float* __restrict__ w2, const float* __restrict__ w3,
    const float* __restrict__ w4)
{
    const int i = blockIdx.x * 256 + threadIdx.x;
    const float* src;
    __half* dst;
    int off;
    if (i < 1048576) {
        src = (i < 524288) ? xq : xr;
        dst = (i < 524288) ? g_xq : g_xr;
        off = i & 524287;
    } else {
        const int j = i - 1048576;
        const int w = j >> 18;
        off = j & 262143;
        const float* ws[5] = {w0, w1, w2, w3, w4};
        src = ws[w];
        dst = g_w16 + (size_t)w * (F * NHD);
    }
    float4 v = ((const float4*)src)[off];
    ((__half2*)dst)[off * 2]     = __floats2half2_rn(v.x, v.y);
    ((__half2*)dst)[off * 2 + 1] = __floats2half2_rn(v.z, v.w);
}

// ---------------------------------------------------------------------------
// f16 GEMM: C = (Ah [+ Al]) @ B + bias   (unchanged from R16)
// ---------------------------------------------------------------------------
#define GEMM_SMEM_BYTES 58368

template <bool SPLIT_A>
__device__ __forceinline__ void gemm_f16_body(
    const __half* __restrict__ Ah, const __half* __restrict__ Al,
    const __half* __restrict__ B,
    const float* __restrict__ bias, float* __restrict__ C,
    __half* __restrict__ C16, float scale,
    int M, int N, int K)
{
    extern __shared__ __half sh[];
    __half* As_h = sh;
    __half* As_l = sh + 10240;
    __half* Bs   = sh + 20480;

    const int t    = threadIdx.x;
    const int lane = t & 31;
    const int w    = t >> 5;
    const int wm   = (w & 3) * 32;
    const int wn   = (w >> 2) * 64;
    const int g    = lane >> 2;
    const int tg   = lane & 3;
    const int m0   = blockIdx.y * 128;
    const int n0   = blockIdx.x * 128;

    float Cr[2][8][4];
#pragma unroll
    for (int mt = 0; mt < 2; mt++)
#pragma unroll
        for (int nt = 0; nt < 8; nt++) {
            Cr[mt][nt][0] = 0.f; Cr[mt][nt][1] = 0.f;
            Cr[mt][nt][2] = 0.f; Cr[mt][nt][3] = 0.f;
        }

    const int fm = t >> 1, fh = (t & 1) * 16;
    const int fk = t >> 3, fv = (t & 7) * 16;

    const __half* gAh = Ah + (size_t)(m0 + fm) * K + fh;
    const __half* gAl = SPLIT_A ? Al + (size_t)(m0 + fm) * K + fh : nullptr;
    const __half* gB  = B  + (size_t)fk * N + n0 + fv;

    const int sa_off = fm * 40 + fh;
    const int sb_off = fk * 136 + fv;

    {
        u32 d;
        d = sptr(As_h + sa_off); cpa16(d, gAh); cpa16(d + 16, gAh + 8);
        if (SPLIT_A) {
            d = sptr(As_l + sa_off); cpa16(d, gAl); cpa16(d + 16, gAl + 8);
        }
        d = sptr(Bs + sb_off);   cpa16(d, gB);  cpa16(d + 16, gB + 8);
        CP_COMMIT();
        CP_WAIT0();
    }
    __syncthreads();

    int buf = 0;
    const int nkc = K / 32;
    for (int kc = 0; kc < nkc; kc++) {
        const bool has = (kc + 1) < nkc;
        if (has) {
            const __half* pAh = gAh + (kc + 1) * 32;
            const __half* pB  = gB + (size_t)(kc + 1) * 32 * N;
            const int nb = buf ^ 1;
            u32 d;
            d = sptr(As_h + nb * 5120 + sa_off); cpa16(d, pAh); cpa16(d + 16, pAh + 8);
            if (SPLIT_A) {
                const __half* pAl = gAl + (kc + 1) * 32;
                d = sptr(As_l + nb * 5120 + sa_off); cpa16(d, pAl); cpa16(d + 16, pAl + 8);
            }
            d = sptr(Bs + nb * 4352 + sb_off);   cpa16(d, pB);  cpa16(d + 16, pB + 8);
            CP_COMMIT();
        }
        const __half* Ab_h = As_h + buf * 5120;
        const __half* Ab_l = As_l + buf * 5120;
        const __half* Bb   = Bs + buf * 4352;

#pragma unroll
        for (int ks2 = 0; ks2 < 2; ks2++) {
            const int ks = ks2 * 16;
            u32 ah[2][4], al[2][4];
#pragma unroll
            for (int mt = 0; mt < 2; mt++) {
                const __half* r0 = Ab_h + (wm + mt * 16 + g) * 40 + ks + 2 * tg;
                ah[mt][0] = *(const u32*)r0;
                ah[mt][1] = *(const u32*)(r0 + 8 * 40);
                ah[mt][2] = *(const u32*)(r0 + 8);
                ah[mt][3] = *(const u32*)(r0 + 8 * 40 + 8);
                if (SPLIT_A) {
                    const __half* r1 = Ab_l + (wm + mt * 16 + g) * 40 + ks + 2 * tg;
                    al[mt][0] = *(const u32*)r1;
                    al[mt][1] = *(const u32*)(r1 + 8 * 40);
                    al[mt][2] = *(const u32*)(r1 + 8);
                    al[mt][3] = *(const u32*)(r1 + 8 * 40 + 8);
                }
            }
            const u32 bb = sptr(Bb + (ks + (lane & 15)) * 136 + wn);
#pragma unroll
            for (int nt = 0; nt < 8; nt++) {
                u32 b0, b1;
                ldm2t(b0, b1, bb + nt * 16);
#pragma unroll
                for (int mt = 0; mt < 2; mt++) {
                    mma_f16(Cr[mt][nt], ah[mt], b0, b1);
                    if (SPLIT_A) mma_f16(Cr[mt][nt], al[mt], b0, b1);
                }
            }
        }

        if (has) {
            CP_WAIT0();
            __syncthreads();
            buf ^= 1;
        }
    }

#pragma unroll
    for (int mt = 0; mt < 2; mt++) {
        const int row = m0 + wm + mt * 16 + g;
#pragma unroll
        for (int nt = 0; nt < 8; nt++) {
            const int col = n0 + wn + nt * 8 + 2 * tg;
            float2 b01 = *(const float2*)&bias[col];
            const float v00 = Cr[mt][nt][0] + b01.x;
            const float v01 = Cr[mt][nt][1] + b01.y;
            const float v10 = Cr[mt][nt][2] + b01.x;
            const float v11 = Cr[mt][nt][3] + b01.y;
            if (C) {
                *(float2*)(C + (size_t)row * N + col)       = make_float2(v00, v01);
                *(float2*)(C + (size_t)(row + 8) * N + col) = make_float2(v10, v11);
            }
            if (C16) {
                *(__half2*)(C16 + (size_t)row * N + col) =
                    __floats2half2_rn(v00 * scale, v01 * scale);
                *(__half2*)(C16 + (size_t)(row + 8) * N + col) =
                    __floats2half2_rn(v10 * scale, v11 * scale);
            }
        }
    }
}

__global__ __launch_bounds__(256, 2) void proj_f16_kernel(
    const float* __restrict__ bq, const float* __restrict__ bk,
    const float* __restrict__ bv, const float* __restrict__ br)
{
    const int z = blockIdx.z;
    const __half* A = (z < 3) ? g_xq : g_xr;
    const __half* B = g_w16 + (size_t)z * (F * NHD);
    const float* bias;
    __half* C16;
    float scale = 1.f;
    switch (z) {
        case 0:  bias = bq; C16 = g_q16; scale = SCQ; break;
        case 1:  bias = bk; C16 = g_k16; break;
        case 2:  bias = bv; C16 = g_v16; break;
        default: bias = br; C16 = g_r16; break;
    }
    gemm_f16_body<false>(A, nullptr, B, bias, nullptr, C16, scale, S, NHD, F);
}

__global__ __launch_bounds__(256, 2) void out_f16_kernel(
    const float* __restrict__ bo, float* __restrict__ out)
{
    gemm_f16_body<true>(g_at_h, g_at_l, g_w16 + (size_t)4 * (F * NHD),
                        bo, out, nullptr, 1.f, S, F, NHD);
}

// ---------------------------------------------------------------------------
// ck[h][j] = SCQ * rw[h].k16[j,h,:],  cr[h][m] = SCQ * rr[h].r16[m,h,:]
// ---------------------------------------------------------------------------
__global__ __launch_bounds__(256) void bias_dots_kernel(
    const float* __restrict__ rwb, const float* __restrict__ rrb)
{
    const int gw   = (blockIdx.x * blockDim.x + threadIdx.x) >> 5;
    const int lane = threadIdx.x & 31;
    const int which = gw >= H * S;
    const int idx   = which ? gw - H * S : gw;
    const int hh = idx >> 11;
    const int j  = idx & (S - 1);
    const float* bias = which ? rrb : rwb;
    const __half* mat = which ? g_r16 : g_k16;
    const float b0 = bias[hh * DH + lane];
    const float b1 = bias[hh * DH + 32 + lane];
    const __half* row = mat + (size_t)j * NHD + hh * DH;
    float s = fmaf(b0, __half2float(row[lane]),
                   b1 * __half2float(row[32 + lane]));
#pragma unroll
    for (int off = 16; off > 0; off >>= 1)
        s += __shfl_xor_sync(0xffffffffu, s, off);
    if (lane == 0) {
        float* dst = which ? g_cr : g_ck;
        dst[hh * S + j] = s * SCQ;
    }
}

// ---------------------------------------------------------------------------
// Causal flash attention, all-f16 MMA (k16), log2-domain softmax.
// R17: software-pipelined fills — K/V double-buffered, RSL circular rows
// prefetched post-AC (safe: rows being overwritten are only read in the
// G-pass of the current tile, complete at that barrier).
// ---------------------------------------------------------------------------
#define KP16 72
#define KVSZ (64 * KP16)
#define GPAD 132
#define SMEM_ATTN ((4*KVSZ + 128*KP16)*2 + (64*GPAD + 128 + 64 + 128)*4)

__global__ __launch_bounds__(256, 2) void attn_kernel()
{
    const int h   = blockIdx.y;
    const int qi0 = (gridDim.x - 1 - blockIdx.x) * 64;

    extern __shared__ float sm[];
    __half* ks16  = (__half*)sm;                 // [2][64*KP16]
    __half* vs16  = ks16 + 2 * KVSZ;             // [2][64*KP16] (+ones col 64)
    __half* rsl16 = vs16 + 2 * KVSZ;             // 128*KP16 (circular)
    float*  G     = (float*)(rsl16 + 128 * KP16);
    float*  crs_s = G + 64 * GPAD;
    float*  cks_s = crs_s + 128;
    float*  mx    = cks_s + 64;

    const int t    = threadIdx.x;
    const int lane = t & 31;
    const int w    = t >> 5;
    const int wp   = w & 3;
    const int half = w >> 2;
    const int g    = lane >> 2;
    const int tg   = lane & 3;
    const int i0   = wp * 16 + g;
    const int hb   = h * DH;
    const int jbase = half * 32;
    const int tile0 = (half == 0) ? (6 - 2 * wp) : (11 - 2 * wp);

    u32 qa[4][4];
    {
        const __half* q0 = &g_q16[(size_t)(qi0 + i0) * NHD + hb];
        const __half* q1 = q0 + 8 * NHD;
#pragma unroll
        for (int k0 = 0; k0 < 4; k0++) {
            qa[k0][0] = *(const u32*)(q0 + k0 * 16 + 2 * tg);
            qa[k0][1] = *(const u32*)(q1 + k0 * 16 + 2 * tg);
            qa[k0][2] = *(const u32*)(q0 + k0 * 16 + 8 + 2 * tg);
            qa[k0][3] = *(const u32*)(q1 + k0 * 16 + 8 + 2 * tg);
        }
    }

    // ones columns for l (col 64 of both V buffers; fills never touch 64..71)
    if (t < 64) {
#pragma unroll
        for (int b = 0; b < 2; b++) {
            __half* p = &vs16[b * KVSZ + t * KP16 + 64];
            p[0] = __float2half(1.f);
#pragma unroll
            for (int i = 1; i < 8; i++) p[i] = __float2half(0.f);
        }
    }

    float O[9][4];
#pragma unroll
    for (int nt = 0; nt < 9; nt++) {
        O[nt][0] = 0.f; O[nt][1] = 0.f; O[nt][2] = 0.f; O[nt][3] = 0.f;
    }
    float m0 = -1e30f, m1 = -1e30f;

    const int nkt = qi0 / 64 + 1;

    // ---- prologue: fill tile 0 into buffer 0 ----
    {
        const int base0 = (S - 1) - qi0 - 63;
#pragma unroll
        for (int it = 0; it < 2; it++) {
            const int idx = t + it * 256;
            const int r = idx >> 3, c8 = (idx & 7) << 3;
            cpa16(sptr(&ks16[r * KP16 + c8]),
                  &g_k16[(size_t)r * NHD + hb + c8]);
            cpa16(sptr(&vs16[r * KP16 + c8]),
                  &g_v16[(size_t)r * NHD + hb + c8]);
        }
        for (int it = 0; it < 4; it++) {
            const int idx = t + it * 256;
            const int row = idx >> 3;
            const int c8  = (idx & 7) << 3;
            int mg = base0 + row;
            if (mg < 0) mg = 0;            // base0 can be negative? base0 = S-1-qi0-63 >= S-1-2047-63... qi0<=1984 -> base0>=... S-1-1984-63=0. OK min 0.
            if (mg > S - 1) mg = S - 1;
            cpa16(sptr(&rsl16[((base0 & 127) + row & 127) * KP16 + c8]),
                  &g_r16[(size_t)mg * NHD + hb + c8]);
        }
        if (t < 64) cks_s[t] = g_ck[h * S + t];
        else if (t < 192) {
            const int mm = t - 64;
            int mg = base0 + mm;
            if (mg > S - 1) mg = S - 1;
            crs_s[mm] = (mm < 127) ? g_cr[h * S + mg] : 0.f;
        }
        CP_COMMIT();
    }

    int buf = 0;
    for (int kt = 0; kt < nkt; kt++) {
        const int kj0   = kt * 64;
        const int base  = (S - 1) + kj0 - qi0 - 63;
        const int rbase = base & 127;
        CP_WAIT0();
        __syncthreads();   // tile kt data visible to all

        __half* ksb = ks16 + buf * KVSZ;
        __half* vsb = vs16 + buf * KVSZ;

        // ---- windowed G = Q @ RSL^T (+cr): 5 tiles ----
        {
            u32 rb[5];
#pragma unroll
            for (int ni = 0; ni < 5; ni++) {
                const int lrow = (rbase + (tile0 + ni) * 8 + (lane & 7)) & 127;
                rb[ni] = sptr(&rsl16[lrow * KP16 + ((lane >> 3) & 1) * 8]);
            }
            float gc[5][4];
#pragma unroll
            for (int ni = 0; ni < 5; ni++) {
                const int col = (tile0 + ni) * 8 + 2 * tg;
                gc[ni][0] = crs_s[col];
                gc[ni][1] = crs_s[col + 1];
                gc[ni][2] = gc[ni][0];
                gc[ni][3] = gc[ni][1];
            }
#pragma unroll
            for (int k0 = 0; k0 < 4; k0++) {
#pragma unroll
                for (int ni = 0; ni < 5; ni++) {
                    u32 b0, b1;
                    ldm2(b0, b1, rb[ni] + k0 * 32);
                    mma_f16(gc[ni], qa[k0], b0, b1);
                }
            }
#pragma unroll
            for (int ni = 0; ni < 5; ni++) {
                const int col = (tile0 + ni) * 8 + 2 * tg;
                *(float2*)&G[i0 * GPAD + col]       = make_float2(gc[ni][0], gc[ni][1]);
                *(float2*)&G[(i0 + 8) * GPAD + col] = make_float2(gc[ni][2], gc[ni][3]);
            }
        }
        pair_bar(wp);

        // ---- AC = Q @ K^T (+ck), own 32-key half ----
        float sc[4][4];
        u32 kb4[4];
#pragma unroll
        for (int nt = 0; nt < 4; nt++) {
            const int col = jbase + nt * 8 + 2 * tg;
            sc[nt][0] = cks_s[col];
            sc[nt][1] = cks_s[col + 1];
            sc[nt][2] = sc[nt][0];
            sc[nt][3] = sc[nt][1];
            kb4[nt] = sptr(&ksb[(jbase + nt * 8 + (lane & 7)) * KP16 +
                                ((lane >> 3) & 1) * 8]);
        }
#pragma unroll
        for (int k0 = 0; k0 < 4; k0++) {
#pragma unroll
            for (int nt = 0; nt < 4; nt++) {
                u32 b0, b1;
                ldm2(b0, b1, kb4[nt] + k0 * 32);
                mma_f16(sc[nt], qa[k0], b0, b1);
            }
        }

        // ---- all warps done reading rsl(G) / ks(AC) / cks / crs ----
        __syncthreads();

        // ---- prefetch tile kt+1 (K/V alt buffer, RSL circular, ck/cr) ----
        if (kt + 1 < nkt) {
            const int kj1   = kj0 + 64;
            const int base1 = base + 64;
            const int rb1   = base1 & 127;
            __half* ksn = ks16 + (buf ^ 1) * KVSZ;
            __half* vsn = vs16 + (buf ^ 1) * KVSZ;
#pragma unroll
            for (int it = 0; it < 2; it++) {
                const int idx = t + it * 256;
                const int r = idx >> 3, c8 = (idx & 7) << 3;
                cpa16(sptr(&ksn[r * KP16 + c8]),
                      &g_k16[(size_t)(kj1 + r) * NHD + hb + c8]);
                cpa16(sptr(&vsn[r * KP16 + c8]),
                      &g_v16[(size_t)(kj1 + r) * NHD + hb + c8]);
            }
#pragma unroll
            for (int it = 0; it < 2; it++) {
                const int idx = t + it * 256;
                const int row = 64 + (idx >> 3);
                const int c8  = (idx & 7) << 3;
                int mg = base1 + row;
                if (mg > S - 1) mg = S - 1;
                cpa16(sptr(&rsl16[((rb1 + row) & 127) * KP16 + c8]),
                      &g_r16[(size_t)mg * NHD + hb + c8]);
            }
            if (t < 64) cks_s[t] = g_ck[h * S + kj1 + t];
            else if (t < 192) {
                const int mm = t - 64;
                int mg = base1 + mm;
                if (mg > S - 1) mg = S - 1;
                crs_s[mm] = (mm < 127) ? g_cr[h * S + mg] : 0.f;
            }
            CP_COMMIT();
        }

        // ---- BD gather + mask + own-half row max ----
        const bool diag = (kt == nkt - 1);
        float rmax0 = -1e30f, rmax1 = -1e30f;
#pragma unroll
        for (int nt = 0; nt < 4; nt++) {
            const int j = jbase + nt * 8 + 2 * tg;
            float s00 = sc[nt][0] + G[i0 * GPAD + 63 + j - i0];
            float s01 = sc[nt][1] + G[i0 * GPAD + 64 + j - i0];
            float s10 = sc[nt][2] + G[(i0 + 8) * GPAD + 55 + j - i0];
            float s11 = sc[nt][3] + G[(i0 + 8) * GPAD + 56 + j - i0];
            if (diag) {
                if (kj0 + j     > qi0 + i0)     s00 = -1e30f;
                if (kj0 + j + 1 > qi0 + i0)     s01 = -1e30f;
                if (kj0 + j     > qi0 + i0 + 8) s10 = -1e30f;
                if (kj0 + j + 1 > qi0 + i0 + 8) s11 = -1e30f;
            }
            sc[nt][0] = s00; sc[nt][1] = s01; sc[nt][2] = s10; sc[nt][3] = s11;
            rmax0 = fmaxf(rmax0, fmaxf(s00, s01));
            rmax1 = fmaxf(rmax1, fmaxf(s10, s11));
        }
        rmax0 = fmaxf(rmax0, __shfl_xor_sync(0xffffffffu, rmax0, 1));
        rmax0 = fmaxf(rmax0, __shfl_xor_sync(0xffffffffu, rmax0, 2));
        rmax1 = fmaxf(rmax1, __shfl_xor_sync(0xffffffffu, rmax1, 1));
        rmax1 = fmaxf(rmax1, __shfl_xor_sync(0xffffffffu, rmax1, 2));

        mx[2 * i0 + half]       = rmax0;
        mx[2 * (i0 + 8) + half] = rmax1;
        pair_bar(wp);
        rmax0 = fmaxf(rmax0, mx[2 * i0 + (half ^ 1)]);
        rmax1 = fmaxf(rmax1, mx[2 * (i0 + 8) + (half ^ 1)]);

        const float newm0 = fmaxf(m0, rmax0);
        const float newm1 = fmaxf(m1, rmax1);
        const float a0 = exp2f(m0 - newm0);
        const float a1 = exp2f(m1 - newm1);
        m0 = newm0; m1 = newm1;
#pragma unroll
        for (int nt = 0; nt < 9; nt++) {
            O[nt][0] *= a0; O[nt][1] *= a0;
            O[nt][2] *= a1; O[nt][3] *= a1;
        }

        // ---- p = 2^(s-m): results ARE the PV a-frag pairs ----
        u32 pp[4][2];
#pragma unroll
        for (int nt = 0; nt < 4; nt++) {
            pp[nt][0] = exp2_f16x2(sc[nt][0] - m0, sc[nt][1] - m0);
            pp[nt][1] = exp2_f16x2(sc[nt][2] - m1, sc[nt][3] - m1);
        }

        // ---- PV (f16 k16): O += P_half @ [V | 1] ----
#pragma unroll
        for (int ki = 0; ki < 2; ki++) {
            const int kb = jbase + ki * 16;
            u32 pa[4];
            pa[0] = pp[2 * ki][0];
            pa[1] = pp[2 * ki][1];
            pa[2] = pp[2 * ki + 1][0];
            pa[3] = pp[2 * ki + 1][1];
            const u32 vb = sptr(vsb + (size_t)(kb + (lane & 15)) * KP16);
#pragma unroll
            for (int nt = 0; nt < 9; nt++) {
                u32 b0, b1;
                ldm2t(b0, b1, vb + nt * 16);
                mma_f16(O[nt], pa, b0, b1);
            }
        }
        buf ^= 1;
    }

    float l0 = __shfl_sync(0xffffffffu, O[8][0], lane & 28);
    float l1 = __shfl_sync(0xffffffffu, O[8][2], lane & 28);

    __syncthreads();
    if (half == 1) {
#pragma unroll
        for (int nt = 0; nt < 8; nt++) {
            const int col = nt * 8 + 2 * tg;
            *(float2*)&G[i0 * GPAD + col]       = make_float2(O[nt][0], O[nt][1]);
            *(float2*)&G[(i0 + 8) * GPAD + col] = make_float2(O[nt][2], O[nt][3]);
        }
        if (tg == 0) {
            cks_s[i0]     = l0;
            cks_s[i0 + 8] = l1;
        }
    }
    __syncthreads();
    if (half == 0) {
        l0 += cks_s[i0];
        l1 += cks_s[i0 + 8];
        const float inv0 = 1.f / l0;
        const float inv1 = 1.f / l1;
#pragma unroll
        for (int nt = 0; nt < 8; nt++) {
            const int col = nt * 8 + 2 * tg;
            float2 p0 = *(const float2*)&G[i0 * GPAD + col];
            float2 p1 = *(const float2*)&G[(i0 + 8) * GPAD + col];
            float o00 = (O[nt][0] + p0.x) * inv0, o01 = (O[nt][1] + p0.y) * inv0;
            float o10 = (O[nt][2] + p1.x) * inv1, o11 = (O[nt][3] + p1.y) * inv1;
            const size_t idx0 = (size_t)(qi0 + i0) * NHD + hb + col;
            const size_t idx1 = (size_t)(qi0 + i0 + 8) * NHD + hb + col;
            __half2 h0 = __floats2half2_rn(o00, o01);
            __half2 h1 = __floats2half2_rn(o10, o11);
            float2 f0 = __half22float2(h0);
            float2 f1 = __half22float2(h1);
            __half2 L0 = __floats2half2_rn(o00 - f0.x, o01 - f0.y);
            __half2 L1 = __floats2half2_rn(o10 - f1.x, o11 - f1.y);
            *(__half2*)&g_at_h[idx0] = h0;
            *(__half2*)&g_at_l[idx0] = L0;
            *(__half2*)&g_at_h[idx1] = h1;
            *(__half2*)&g_at_l[idx1] = L1;
        }
    }
}

// ---------------------------------------------------------------------------
extern "C" void kernel_launch(void* const* d_in, const int* in_sizes, int n_in,
                              void* d_out, int out_size)
{
    const float* inputs_q = (const float*)d_in[0];
    const float* pos_emb  = (const float*)d_in[1];
    const float* r_w_bias = (const float*)d_in[2];
    const float* r_r_bias = (const float*)d_in[3];
    const float* Wq = (const float*)d_in[4];
    const float* bq = (const float*)d_in[5];
    const float* Wk = (const float*)d_in[6];
    const float* bk = (const float*)d_in[7];
    const float* Wv = (const float*)d_in[8];
    const float* bv = (const float*)d_in[9];
    const float* Wr = (const float*)d_in[10];
    const float* br = (const float*)d_in[11];
    const float* Wo = (const float*)d_in[12];
    const float* bo = (const float*)d_in[13];
    float* out = (float*)d_out;

    cudaFuncSetAttribute(attn_kernel,
                         cudaFuncAttributeMaxDynamicSharedMemorySize, SMEM_ATTN);
    cudaFuncSetAttribute(proj_f16_kernel,
                         cudaFuncAttributeMaxDynamicSharedMemorySize, GEMM_SMEM_BYTES);
    cudaFuncSetAttribute(out_f16_kernel,
                         cudaFuncAttributeMaxDynamicSharedMemorySize, GEMM_SMEM_BYTES);

    split_kernel<<<(2 * 524288 + 5 * 262144) / 256, 256>>>(
        inputs_q, pos_emb, Wq, Wk, Wv, Wr, Wo);

    proj_f16_kernel<<<dim3(NHD / 128, S / 128, 4), 256, GEMM_SMEM_BYTES>>>(
        bq, bk, bv, br);

    bias_dots_kernel<<<(2 * H * S * 32) / 256, 256>>>(r_w_bias, r_r_bias);

    attn_kernel<<<dim3(S / 64, H), 256, SMEM_ATTN>>>();

    out_f16_kernel<<<dim3(F / 128, S / 128), 256, GEMM_SMEM_BYTES>>>(bo, out);
}